// round 4
// baseline (speedup 1.0000x reference)
#include <cuda_runtime.h>
#include <cuda_bf16.h>

#define N_NODES 50000
#define EMBED_DIM 128
#define N_EDGES 500000

// Scratch: device globals (sanctioned scratch mechanism; no runtime allocation).
__device__ float g_dis[N_NODES];                    // degree -> rsqrt(degree)
__device__ float g_agg[N_NODES * EMBED_DIM];        // aggregation buffer
__device__ float g_h[N_NODES * EMBED_DIM];          // layer-1 activations

// ---------------------------------------------------------------------------
// Degree / normalization
// ---------------------------------------------------------------------------
__global__ void k_deg_init() {
    int i = blockIdx.x * blockDim.x + threadIdx.x;
    if (i < N_NODES) g_dis[i] = 1.0f;  // self loop contributes 1
}

__global__ void k_deg_count(const int* __restrict__ ei) {
    int e = blockIdx.x * blockDim.x + threadIdx.x;
    if (e < N_EDGES) {
        unsigned d = (unsigned)ei[N_EDGES + e];
        if (d < N_NODES) atomicAdd(&g_dis[d], 1.0f);
    }
}

__global__ void k_dis() {
    int i = blockIdx.x * blockDim.x + threadIdx.x;
    if (i < N_NODES) g_dis[i] = rsqrtf(g_dis[i]);
}

// ---------------------------------------------------------------------------
// agg[i] = dis[i]^2 * in[i]   (self-loop term; also initializes the buffer)
// in = x (use_h=0) or g_h (use_h=1). One float4 per thread.
// ---------------------------------------------------------------------------
__global__ void k_agg_init(const float* __restrict__ x, int use_h) {
    int t = blockIdx.x * blockDim.x + threadIdx.x;
    if (t >= N_NODES * 32) return;
    const float* in = use_h ? g_h : x;
    int node = t >> 5;
    int q = t & 31;
    float c = g_dis[node];
    c = c * c;
    float4 v = ((const float4*)(in + (size_t)node * EMBED_DIM))[q];
    v.x *= c; v.y *= c; v.z *= c; v.w *= c;
    ((float4*)(g_agg + (size_t)node * EMBED_DIM))[q] = v;
}

// ---------------------------------------------------------------------------
// Edge scatter: warp per edge; lane handles a float4 slice.
// agg[dst] += dis[src]*dis[dst] * in[src]
// atomicAdd with unused result -> REDG.ADD.F32 (no return trip)
// ---------------------------------------------------------------------------
__global__ void k_scatter(const float* __restrict__ x,
                          const int* __restrict__ ei, int use_h) {
    int idx = blockIdx.x * blockDim.x + threadIdx.x;
    int e = idx >> 5;
    if (e >= N_EDGES) return;
    const float* in = use_h ? g_h : x;
    int lane = idx & 31;
    unsigned s = (unsigned)ei[e];
    unsigned d = (unsigned)ei[N_EDGES + e];
    if (s >= N_NODES || d >= N_NODES) return;   // defensive: never crash
    float nm = g_dis[s] * g_dis[d];
    float4 v = ((const float4*)(in + (size_t)s * EMBED_DIM))[lane];
    float* dst = g_agg + (size_t)d * EMBED_DIM + lane * 4;
    atomicAdd(dst + 0, nm * v.x);
    atomicAdd(dst + 1, nm * v.y);
    atomicAdd(dst + 2, nm * v.z);
    atomicAdd(dst + 3, nm * v.w);
}

// ---------------------------------------------------------------------------
// dst[r,:] = tanh(g_agg[r,:] @ W + b)  for 64 rows per block.
// 256 threads: warp w owns rows w*8..w*8+7, lane owns cols lane*4..lane*4+3.
// dst = g_h (to_h=1) or `out` param (to_h=0).
// ---------------------------------------------------------------------------
__global__ __launch_bounds__(256) void k_gemm_bias_tanh(
    const float* __restrict__ W, const float* __restrict__ b,
    float* __restrict__ out, int to_h)
{
    __shared__ float As[64][EMBED_DIM];
    float* dst = to_h ? g_h : out;
    int row0 = blockIdx.x * 64;
    int tid = threadIdx.x;

    // Load A tile (coalesced). N_NODES=50000 is not a multiple of 64: guard.
    #pragma unroll
    for (int i = 0; i < 32; i++) {
        int idx = tid + i * 256;
        int r = idx >> 7, k = idx & 127;
        int gr = row0 + r;
        As[r][k] = (gr < N_NODES) ? g_agg[(size_t)gr * EMBED_DIM + k] : 0.0f;
    }
    __syncthreads();

    int warp = tid >> 5, lane = tid & 31;
    int r0 = warp * 8;
    int c0 = lane * 4;

    float acc[8][4];
    #pragma unroll
    for (int j = 0; j < 8; j++)
        #pragma unroll
        for (int c = 0; c < 4; c++) acc[j][c] = 0.0f;

    #pragma unroll 8
    for (int k = 0; k < EMBED_DIM; k++) {
        float4 w = *(const float4*)(W + (size_t)k * EMBED_DIM + c0);
        #pragma unroll
        for (int j = 0; j < 8; j++) {
            float a = As[r0 + j][k];   // warp-uniform broadcast
            acc[j][0] += a * w.x;
            acc[j][1] += a * w.y;
            acc[j][2] += a * w.z;
            acc[j][3] += a * w.w;
        }
    }

    float4 bb = *(const float4*)(b + c0);
    #pragma unroll
    for (int j = 0; j < 8; j++) {
        int gr = row0 + r0 + j;
        if (gr < N_NODES) {
            float4 o;
            o.x = tanhf(acc[j][0] + bb.x);
            o.y = tanhf(acc[j][1] + bb.y);
            o.z = tanhf(acc[j][2] + bb.z);
            o.w = tanhf(acc[j][3] + bb.w);
            *(float4*)(dst + (size_t)gr * EMBED_DIM + c0) = o;
        }
    }
}

// ---------------------------------------------------------------------------
// Copy x -> init_embeds output slot (only launched if d_out has room)
// ---------------------------------------------------------------------------
__global__ void k_copy(const float* __restrict__ src, float* __restrict__ dst) {
    int t = blockIdx.x * blockDim.x + threadIdx.x;
    if (t < N_NODES * 32) {
        ((float4*)dst)[t] = ((const float4*)src)[t];
    }
}

extern "C" void kernel_launch(void* const* d_in, const int* in_sizes, int n_in,
                              void* d_out, int out_size) {
    const float* x  = (const float*)d_in[0];
    const int*   ei = (const int*)d_in[1];          // int32 per harness dtype rules
    const float* W1 = (const float*)d_in[2];
    const float* b1 = (const float*)d_in[3];
    const float* W2 = (const float*)d_in[4];
    const float* b2 = (const float*)d_in[5];
    float* out = (float*)d_out;

    const int NT = 256;
    int blksN   = (N_NODES + NT - 1) / NT;
    int blksE   = (N_EDGES + NT - 1) / NT;
    int blksND  = (N_NODES * 32 + NT - 1) / NT;
    int blksSc  = (N_EDGES * 32 + NT - 1) / NT;
    int blksG   = (N_NODES + 63) / 64;

    // normalization
    k_deg_init<<<blksN, NT>>>();
    k_deg_count<<<blksE, NT>>>(ei);
    k_dis<<<blksN, NT>>>();

    // second output (identity init embeds) — only if d_out holds the tuple
    if (out_size >= 2 * N_NODES * EMBED_DIM) {
        k_copy<<<blksND, NT>>>(x, out + (size_t)N_NODES * EMBED_DIM);
    }

    // layer 1: aggregate(x) then transform -> g_h
    k_agg_init<<<blksND, NT>>>(x, 0);
    k_scatter<<<blksSc, NT>>>(x, ei, 0);
    k_gemm_bias_tanh<<<blksG, NT>>>(W1, b1, out, 1);

    // layer 2: aggregate(g_h) then transform -> out
    k_agg_init<<<blksND, NT>>>(x, 1);
    k_scatter<<<blksSc, NT>>>(x, ei, 1);
    k_gemm_bias_tanh<<<blksG, NT>>>(W2, b2, out, 0);
}

// round 5
// speedup vs baseline: 2.2179x; 2.2179x over previous
#include <cuda_runtime.h>
#include <cuda_bf16.h>

#define N_NODES 50000
#define EMBED_DIM 128
#define N_EDGES 500000
#define NBLK ((N_NODES + 255) / 256)   // 196 scan blocks

// Scratch: device globals (no runtime allocation allowed).
__device__ int   g_cnt[N_NODES];          // in-degree histogram (excl. self loop)
__device__ int   g_bsum[NBLK];            // block sums for scan
__device__ int   g_rowstart[N_NODES + 1]; // CSR row offsets
__device__ int   g_cursor[N_NODES];       // fill cursors
__device__ int   g_col[N_EDGES];          // CSR column (src node)
__device__ float g_val[N_EDGES];          // per-edge norm dis[s]*dis[d]
__device__ float g_dis[N_NODES];          // rsqrt(degree incl self loop)
__device__ float g_agg[N_NODES * EMBED_DIM];
__device__ float g_h[N_NODES * EMBED_DIM];

// ---------------------------------------------------------------------------
// CSR build
// ---------------------------------------------------------------------------
__global__ void k_zero_cnt() {
    int i = blockIdx.x * blockDim.x + threadIdx.x;
    if (i < N_NODES) g_cnt[i] = 0;
}

__global__ void k_hist(const int* __restrict__ ei) {
    int e = blockIdx.x * blockDim.x + threadIdx.x;
    if (e < N_EDGES) {
        unsigned d = (unsigned)ei[N_EDGES + e];
        if (d < N_NODES) atomicAdd(&g_cnt[d], 1);
    }
}

__global__ __launch_bounds__(256) void k_blocksum() {
    __shared__ int sh[256];
    int t = threadIdx.x;
    int i = blockIdx.x * 256 + t;
    sh[t] = (i < N_NODES) ? g_cnt[i] : 0;
    __syncthreads();
    #pragma unroll
    for (int off = 128; off > 0; off >>= 1) {
        if (t < off) sh[t] += sh[t + off];
        __syncthreads();
    }
    if (t == 0) g_bsum[blockIdx.x] = sh[0];
}

__global__ __launch_bounds__(256) void k_scan_bsums() {
    __shared__ int sh[256];
    int t = threadIdx.x;
    int v = (t < NBLK) ? g_bsum[t] : 0;
    sh[t] = v;
    __syncthreads();
    #pragma unroll
    for (int off = 1; off < 256; off <<= 1) {
        int add = (t >= off) ? sh[t - off] : 0;
        __syncthreads();
        sh[t] += add;
        __syncthreads();
    }
    if (t < NBLK) g_bsum[t] = sh[t] - v;   // exclusive
}

__global__ __launch_bounds__(256) void k_scan_final() {
    __shared__ int sh[256];
    int t = threadIdx.x;
    int i = blockIdx.x * 256 + t;
    int v = (i < N_NODES) ? g_cnt[i] : 0;
    sh[t] = v;
    __syncthreads();
    #pragma unroll
    for (int off = 1; off < 256; off <<= 1) {
        int add = (t >= off) ? sh[t - off] : 0;
        __syncthreads();
        sh[t] += add;
        __syncthreads();
    }
    if (i < N_NODES) {
        int rs = g_bsum[blockIdx.x] + sh[t] - v;  // exclusive global offset
        g_rowstart[i] = rs;
        g_cursor[i]   = rs;
        g_dis[i]      = rsqrtf((float)(v + 1));   // +1 self loop
    }
    if (i == 0) g_rowstart[N_NODES] = N_EDGES;
}

__global__ void k_fill(const int* __restrict__ ei) {
    int e = blockIdx.x * blockDim.x + threadIdx.x;
    if (e >= N_EDGES) return;
    unsigned s = (unsigned)ei[e];
    unsigned d = (unsigned)ei[N_EDGES + e];
    if (s >= N_NODES || d >= N_NODES) return;
    int pos = atomicAdd(&g_cursor[d], 1);
    g_col[pos] = s;
    g_val[pos] = g_dis[s] * g_dis[d];
}

// ---------------------------------------------------------------------------
// Gather-aggregate: warp per node, lane owns a float4 slice.
// agg[i] = dis[i]^2 * in[i] + sum_{j->i} val_j * in[src_j]
// ---------------------------------------------------------------------------
__global__ __launch_bounds__(256) void k_gather(const float* __restrict__ x, int use_h) {
    int idx = blockIdx.x * blockDim.x + threadIdx.x;
    int node = idx >> 5;
    if (node >= N_NODES) return;
    const float* in = use_h ? g_h : x;
    int lane = idx & 31;

    float di = g_dis[node];
    float c = di * di;
    float4 acc = ((const float4*)(in + (size_t)node * EMBED_DIM))[lane];
    acc.x *= c; acc.y *= c; acc.z *= c; acc.w *= c;

    int j   = g_rowstart[node];
    int end = g_rowstart[node + 1];

    // unroll by 2 for MLP
    for (; j + 2 <= end; j += 2) {
        int   s0 = g_col[j],     s1 = g_col[j + 1];
        float n0 = g_val[j],     n1 = g_val[j + 1];
        float4 v0 = ((const float4*)(in + (size_t)s0 * EMBED_DIM))[lane];
        float4 v1 = ((const float4*)(in + (size_t)s1 * EMBED_DIM))[lane];
        acc.x += n0 * v0.x + n1 * v1.x;
        acc.y += n0 * v0.y + n1 * v1.y;
        acc.z += n0 * v0.z + n1 * v1.z;
        acc.w += n0 * v0.w + n1 * v1.w;
    }
    if (j < end) {
        int   s0 = g_col[j];
        float n0 = g_val[j];
        float4 v0 = ((const float4*)(in + (size_t)s0 * EMBED_DIM))[lane];
        acc.x += n0 * v0.x; acc.y += n0 * v0.y;
        acc.z += n0 * v0.z; acc.w += n0 * v0.w;
    }
    ((float4*)(g_agg + (size_t)node * EMBED_DIM))[lane] = acc;
}

// ---------------------------------------------------------------------------
// dst[r,:] = tanh(g_agg[r,:] @ W + b)  for 64 rows per block.
// ---------------------------------------------------------------------------
__global__ __launch_bounds__(256) void k_gemm_bias_tanh(
    const float* __restrict__ W, const float* __restrict__ b,
    float* __restrict__ out, int to_h)
{
    __shared__ float As[64][EMBED_DIM];
    float* dst = to_h ? g_h : out;
    int row0 = blockIdx.x * 64;
    int tid = threadIdx.x;

    #pragma unroll
    for (int i = 0; i < 32; i++) {
        int idx = tid + i * 256;
        int r = idx >> 7, k = idx & 127;
        int gr = row0 + r;
        As[r][k] = (gr < N_NODES) ? g_agg[(size_t)gr * EMBED_DIM + k] : 0.0f;
    }
    __syncthreads();

    int warp = tid >> 5, lane = tid & 31;
    int r0 = warp * 8;
    int c0 = lane * 4;

    float acc[8][4];
    #pragma unroll
    for (int jj = 0; jj < 8; jj++)
        #pragma unroll
        for (int c = 0; c < 4; c++) acc[jj][c] = 0.0f;

    #pragma unroll 8
    for (int k = 0; k < EMBED_DIM; k++) {
        float4 w = *(const float4*)(W + (size_t)k * EMBED_DIM + c0);
        #pragma unroll
        for (int jj = 0; jj < 8; jj++) {
            float a = As[r0 + jj][k];
            acc[jj][0] += a * w.x;
            acc[jj][1] += a * w.y;
            acc[jj][2] += a * w.z;
            acc[jj][3] += a * w.w;
        }
    }

    float4 bb = *(const float4*)(b + c0);
    #pragma unroll
    for (int jj = 0; jj < 8; jj++) {
        int gr = row0 + r0 + jj;
        if (gr < N_NODES) {
            float4 o;
            o.x = tanhf(acc[jj][0] + bb.x);
            o.y = tanhf(acc[jj][1] + bb.y);
            o.z = tanhf(acc[jj][2] + bb.z);
            o.w = tanhf(acc[jj][3] + bb.w);
            *(float4*)(dst + (size_t)gr * EMBED_DIM + c0) = o;
        }
    }
}

__global__ void k_copy(const float* __restrict__ src, float* __restrict__ dst) {
    int t = blockIdx.x * blockDim.x + threadIdx.x;
    if (t < N_NODES * 32) {
        ((float4*)dst)[t] = ((const float4*)src)[t];
    }
}

extern "C" void kernel_launch(void* const* d_in, const int* in_sizes, int n_in,
                              void* d_out, int out_size) {
    const float* x  = (const float*)d_in[0];
    const int*   ei = (const int*)d_in[1];
    const float* W1 = (const float*)d_in[2];
    const float* b1 = (const float*)d_in[3];
    const float* W2 = (const float*)d_in[4];
    const float* b2 = (const float*)d_in[5];
    float* out = (float*)d_out;

    const int NT = 256;
    int blksN  = (N_NODES + NT - 1) / NT;        // 196
    int blksE  = (N_EDGES + NT - 1) / NT;        // 1954
    int blksND = (N_NODES * 32 + NT - 1) / NT;   // 6250 (float4 granularity)
    int blksG  = (N_NODES + 63) / 64;            // 782

    // CSR build + normalization
    k_zero_cnt<<<blksN, NT>>>();
    k_hist<<<blksE, NT>>>(ei);
    k_blocksum<<<NBLK, NT>>>();
    k_scan_bsums<<<1, NT>>>();
    k_scan_final<<<NBLK, NT>>>();
    k_fill<<<blksE, NT>>>(ei);

    // second output (identity init embeds)
    if (out_size >= 2 * N_NODES * EMBED_DIM) {
        k_copy<<<blksND, NT>>>(x, out + (size_t)N_NODES * EMBED_DIM);
    }

    // layer 1
    k_gather<<<blksND, NT>>>(x, 0);
    k_gemm_bias_tanh<<<blksG, NT>>>(W1, b1, out, 1);

    // layer 2
    k_gather<<<blksND, NT>>>(x, 1);
    k_gemm_bias_tanh<<<blksG, NT>>>(W2, b2, out, 0);
}